// round 12
// baseline (speedup 1.0000x reference)
#include <cuda_runtime.h>
#include <cuda_bf16.h>
#include <math.h>
#include <stdint.h>

// ContrastLoss: feat [4,64,512,512] f32, gt [4,19,512,512] i32 -> scalar f32

#define NPIX   (4 * 262144)
#define HW     262144
#define KCLS   19
#define CCH    64
#define TAUF   0.07f
#define LOG2E  1.4426950408889634f
#define CH64   16384               // NPIX / 64 chunks

// -------- device scratch --------
__device__ float    g_k0[KCLS * CCH];
__device__ unsigned g_maskbuf[NPIX];
__device__ int      g_cnt[1024];
__device__ double   g_loss;

// ======== bf16 hi/lo pack: low16 = bf16(f), high16 = bf16(f - float(bf16(f))) ====
__device__ __forceinline__ uint32_t hilo(float f) {
    uint32_t h;
    asm("cvt.rn.bf16x2.f32 %0, %1, %2;" : "=r"(h) : "f"(0.f), "f"(f));
    const float hf = __uint_as_float(h << 16);
    const float lo = f - hf;
    uint32_t r;
    asm("cvt.rn.bf16x2.f32 %0, %1, %2;" : "=r"(r) : "f"(lo), "f"(f));
    return r;
}
// both halves = bf16(f)
__device__ __forceinline__ uint32_t bdup(float f) {
    uint32_t r;
    asm("cvt.rn.bf16x2.f32 %0, %1, %1;" : "=r"(r) : "f"(f));
    return r;
}

// ======== warp MMA m16n8k16 bf16 ========
__device__ __forceinline__ void mma16816(float* d, uint32_t a0, uint32_t a1,
                                         uint32_t a2, uint32_t a3,
                                         uint32_t b0, uint32_t b1) {
    asm volatile(
        "mma.sync.aligned.m16n8k16.row.col.f32.bf16.bf16.f32 "
        "{%0,%1,%2,%3}, {%4,%5,%6,%7}, {%8,%9}, {%0,%1,%2,%3};"
        : "+f"(d[0]), "+f"(d[1]), "+f"(d[2]), "+f"(d[3])
        : "r"(a0), "r"(a1), "r"(a2), "r"(a3), "r"(b0), "r"(b1));
}

// -------- launch 1: zero accumulators --------
__global__ void k_zero() {
    int t = blockIdx.x * 256 + threadIdx.x;
    if (t < KCLS * CCH) g_k0[t] = 0.f;
    if (t == 0) g_loss = 0.0;
}

// -------- launch 0: build 19-bit pixel masks + per-block pos counts --------
__global__ __launch_bounds__(256) void k_mask(const int* __restrict__ gt) {
    const int p4 = (blockIdx.x * 256 + threadIdx.x) * 4;   // 1024 blocks exactly
    const int b  = p4 >> 18;
    const int hw = p4 & (HW - 1);
    unsigned m0 = 0, m1 = 0, m2 = 0, m3 = 0;
#pragma unroll
    for (int k = 0; k < KCLS; k++) {
        const int4 g = *reinterpret_cast<const int4*>(
            gt + (size_t)(b * KCLS + k) * HW + hw);
        m0 |= (unsigned)(g.x == 1) << k;
        m1 |= (unsigned)(g.y == 1) << k;
        m2 |= (unsigned)(g.z == 1) << k;
        m3 |= (unsigned)(g.w == 1) << k;
    }
    *reinterpret_cast<uint4*>(&g_maskbuf[p4]) = make_uint4(m0, m1, m2, m3);
    int cnt = __popc(m0) + __popc(m1) + __popc(m2) + __popc(m3);
#pragma unroll
    for (int o = 16; o; o >>= 1) cnt += __shfl_xor_sync(0xffffffffu, cnt, o);
    __shared__ int sc[8];
    if ((threadIdx.x & 31) == 0) sc[threadIdx.x >> 5] = cnt;
    __syncthreads();
    if (threadIdx.x == 0) {
        int s = 0;
#pragma unroll
        for (int w = 0; w < 8; w++) s += sc[w];
        g_cnt[blockIdx.x] = s;
    }
}

// -------- launch 2: smem-staged HMMA prototype GEMM (validated R10) --------
__global__ __launch_bounds__(256, 4) void k_proto_mma(const float* __restrict__ feat) {
    __shared__ uint32_t sA[64 * 80];
    __shared__ uint32_t sM[64];
    __shared__ float    sk0[KCLS * CCH];

    const int tid  = threadIdx.x;
    const int w    = tid >> 5;
    const int lane = tid & 31;
    const int g    = lane >> 2;
    const int t    = lane & 3;
    const int chb  = (w & 3) * 16;
    const int hb   = (w >> 2) * 32;
    const int sc_hi = lane >> 4;
    const int sc_px = (lane & 15) * 4;

    for (int i = tid; i < KCLS * CCH; i += 256) sk0[i] = 0.f;

    float d0[4] = {0.f, 0.f, 0.f, 0.f};
    float d1[4] = {0.f, 0.f, 0.f, 0.f};
    float d2[4] = {0.f, 0.f, 0.f, 0.f};

    for (int chunk = blockIdx.x; chunk < CH64; chunk += gridDim.x) {
        const int P  = chunk * 64;
        const int b  = P >> 18;
        const int hw = P & (HW - 1);
        __syncthreads();

#pragma unroll
        for (int i = 0; i < 4; i++) {
            const int ch = w * 8 + 2 * i + sc_hi;
            const float4 f = *reinterpret_cast<const float4*>(
                feat + (size_t)(b * CCH + ch) * HW + hw + sc_px);
            const uint32_t h0 = hilo(f.x);
            const uint32_t h1 = hilo(f.y);
            const uint32_t h2 = hilo(f.z);
            const uint32_t h3 = hilo(f.w);
            const int word = ch * 80 + (sc_px ^ ((ch & 3) << 3));
            *reinterpret_cast<uint4*>(&sA[word]) = make_uint4(h0, h1, h2, h3);
        }
        if (tid < 16)
            *reinterpret_cast<uint4*>(&sM[tid * 4]) =
                *reinterpret_cast<const uint4*>(&g_maskbuf[P + tid * 4]);
        __syncthreads();

#pragma unroll
        for (int s = 0; s < 4; s++) {
            const int px = hb + 8 * s + 2 * t;
            const int sw = px ^ ((g & 3) << 3);
            const uint2 A0 = *reinterpret_cast<const uint2*>(&sA[(chb + g) * 80 + sw]);
            const uint2 A1 = *reinterpret_cast<const uint2*>(&sA[(chb + g + 8) * 80 + sw]);
            const uint2 M  = *reinterpret_cast<const uint2*>(&sM[px]);
            {
                const uint32_t b0 = ((M.x >> g) & 1u) * 0x3F803F80u;
                const uint32_t b1 = ((M.y >> g) & 1u) * 0x3F803F80u;
                mma16816(d0, A0.x, A1.x, A0.y, A1.y, b0, b1);
            }
            {
                const uint32_t b0 = ((M.x >> (8 + g)) & 1u) * 0x3F803F80u;
                const uint32_t b1 = ((M.y >> (8 + g)) & 1u) * 0x3F803F80u;
                mma16816(d1, A0.x, A1.x, A0.y, A1.y, b0, b1);
            }
            {
                const uint32_t b0 = ((M.x >> (16 + g)) & 1u) * 0x3F803F80u;
                const uint32_t b1 = ((M.y >> (16 + g)) & 1u) * 0x3F803F80u;
                mma16816(d2, A0.x, A1.x, A0.y, A1.y, b0, b1);
            }
        }
    }

    __syncthreads();
    {
        const int c0 = chb + g;
        const int c1 = chb + g + 8;
        const int k0c = 2 * t, k1c = 2 * t + 1;
        atomicAdd(&sk0[(k0c)     * CCH + c0], d0[0]);
        atomicAdd(&sk0[(k1c)     * CCH + c0], d0[1]);
        atomicAdd(&sk0[(k0c)     * CCH + c1], d0[2]);
        atomicAdd(&sk0[(k1c)     * CCH + c1], d0[3]);
        atomicAdd(&sk0[(8 + k0c) * CCH + c0], d1[0]);
        atomicAdd(&sk0[(8 + k1c) * CCH + c0], d1[1]);
        atomicAdd(&sk0[(8 + k0c) * CCH + c1], d1[2]);
        atomicAdd(&sk0[(8 + k1c) * CCH + c1], d1[3]);
        if (16 + k0c < KCLS) {
            atomicAdd(&sk0[(16 + k0c) * CCH + c0], d2[0]);
            atomicAdd(&sk0[(16 + k0c) * CCH + c1], d2[2]);
        }
        if (16 + k1c < KCLS) {
            atomicAdd(&sk0[(16 + k1c) * CCH + c0], d2[1]);
            atomicAdd(&sk0[(16 + k1c) * CCH + c1], d2[3]);
        }
    }
    __syncthreads();
    for (int i = tid; i < KCLS * CCH; i += 256) atomicAdd(&g_k0[i], sk0[i]);
}

// -------- per-pixel softmax/NLL (tau pre-folded into prototypes) --------
__device__ __forceinline__ float pix_loss(const float* __restrict__ l,
                                          float ssum, unsigned m) {
    const float sc = 1.f / fmaxf(sqrtf(ssum), 1e-12f);
    float v[KCLS];
    float mx = -1e30f;
#pragma unroll
    for (int k = 0; k < KCLS; k++) {
        v[k] = l[k] * sc;
        mx = fmaxf(mx, v[k]);
    }
    float se = 0.f, sl = 0.f;
#pragma unroll
    for (int k = 0; k < KCLS; k++) {
        se += exp2f((v[k] - mx) * LOG2E);
        if (m & (1u << k)) sl += v[k];
    }
    return (float)__popc(m) * (mx + logf(se)) - sl;
}

// -------- launch 3: HMMA logits + softmax NLL (PROFILED SLOT) --------
// logits[px][cls] = feat[px][ch] . proto[cls][ch], K = 192 u16 slots:
//   word p (0..63):  A=(fhi_p, flo_p)          B=(phi_p, phi_p)
//   word 64+j:       A=(fhi_{2j}, fhi_{2j+1})  B=(plo_{2j}, plo_{2j+1})
// ssp race fixed: zeroed in preamble; softmax phase resets its slot after use.
__global__ __launch_bounds__(256, 3) void k_loss_mma(const float* __restrict__ feat) {
    __shared__ uint32_t sA[96 * 68];        // 26.1 KB
    __shared__ uint32_t sB[24 * 100];       // 9.6 KB
    __shared__ float    slog[2][64 * 26];   // 13.3 KB
    __shared__ float    ssp[64];
    __shared__ uint32_t sM[64];
    __shared__ float    sinv[32];

    const int tid  = threadIdx.x;
    const int w    = tid >> 5;
    const int lane = tid & 31;
    const int g    = lane >> 2;
    const int t    = lane & 3;
    const int sc_hi = lane >> 4;
    const int sc_px = (lane & 15) * 4;
    const int half = w >> 2;
    const int pxb  = (w & 3) * 16;

    // ---- preamble: prototype norms, build B (phi dup + plo pairs), zero ssp ----
    if (tid < KCLS) {
        float s = 0.f;
#pragma unroll
        for (int c = 0; c < CCH; c++) {
            const float v = g_k0[tid * CCH + c];
            s = fmaf(v, v, s);
        }
        sinv[tid] = 1.f / (fmaxf(sqrtf(s), 1e-12f) * TAUF);
    }
    if (tid < 64) ssp[tid] = 0.f;
    __syncthreads();
    for (int idx = tid; idx < 24 * CCH; idx += 256) {
        const int k = idx >> 6;
        const int c = idx & 63;
        const float p = (k < KCLS) ? g_k0[k * CCH + c] * sinv[k] : 0.f;
        const uint32_t wph = bdup(p);
        sB[k * 100 + c] = wph;
        const float phf = __uint_as_float(wph << 16);
        const uint32_t wpl = bdup(p - phf);
        reinterpret_cast<uint16_t*>(&sB[k * 100 + 64 + (c >> 1)])[c & 1] =
            (uint16_t)(wpl & 0xFFFFu);
    }

    float lsum = 0.f;
    for (int chunk = blockIdx.x; chunk < CH64; chunk += gridDim.x) {
        const int P  = chunk * 64;
        const int b  = P >> 18;
        const int hw = P & (HW - 1);
        __syncthreads();   // bar: prev softmax (incl. ssp reset) done; sB ready

        // ---- stage: feat -> sA, ss partials, masks ----
        if (tid < 16)
            *reinterpret_cast<uint4*>(&sM[tid * 4]) =
                *reinterpret_cast<const uint4*>(&g_maskbuf[P + tid * 4]);
        float ss4[4] = {0.f, 0.f, 0.f, 0.f};
#pragma unroll
        for (int i = 0; i < 4; i++) {
            const int ch = w * 8 + 2 * i + sc_hi;
            const float4 f = *reinterpret_cast<const float4*>(
                feat + (size_t)(b * CCH + ch) * HW + hw + sc_px);
            uint32_t hv0 = hilo(f.x), hv1 = hilo(f.y), hv2 = hilo(f.z), hv3 = hilo(f.w);
            *reinterpret_cast<uint4*>(&sA[ch * 68 + sc_px]) =
                make_uint4(hv0, hv1, hv2, hv3);
            ss4[0] = fmaf(f.x, f.x, ss4[0]);
            ss4[1] = fmaf(f.y, f.y, ss4[1]);
            ss4[2] = fmaf(f.z, f.z, ss4[2]);
            ss4[3] = fmaf(f.w, f.w, ss4[3]);
            // fhi pair words (row 64 + w*4 + i): (fhi_even, fhi_odd)
            const uint32_t p0 = __shfl_xor_sync(0xffffffffu, hv0, 16);
            const uint32_t p1 = __shfl_xor_sync(0xffffffffu, hv1, 16);
            const uint32_t p2 = __shfl_xor_sync(0xffffffffu, hv2, 16);
            const uint32_t p3 = __shfl_xor_sync(0xffffffffu, hv3, 16);
            if (sc_hi == 0) {
                const int r2 = (64 + w * 4 + i) * 68 + sc_px;
                *reinterpret_cast<uint4*>(&sA[r2]) = make_uint4(
                    (hv0 & 0xFFFFu) | (p0 << 16),
                    (hv1 & 0xFFFFu) | (p1 << 16),
                    (hv2 & 0xFFFFu) | (p2 << 16),
                    (hv3 & 0xFFFFu) | (p3 << 16));
            }
        }
        // ss: combine hi-pair, then smem atomics (ssp pre-zeroed, race-free)
#pragma unroll
        for (int j = 0; j < 4; j++)
            ss4[j] += __shfl_xor_sync(0xffffffffu, ss4[j], 16);
        if (sc_hi == 0) {
#pragma unroll
            for (int j = 0; j < 4; j++)
                atomicAdd(&ssp[sc_px + j], ss4[j]);
        }
        __syncthreads();

        // ---- MMA: 6 K-steps x 3 n-groups ----
        float dfr[3][4];
#pragma unroll
        for (int n = 0; n < 3; n++)
#pragma unroll
            for (int q = 0; q < 4; q++) dfr[n][q] = 0.f;
#pragma unroll
        for (int s6 = 0; s6 < 6; s6++) {
            const int s = half * 6 + s6;
            const uint32_t a0 = sA[(8 * s + t) * 68 + pxb + g];
            const uint32_t a1 = sA[(8 * s + t) * 68 + pxb + g + 8];
            const uint32_t a2 = sA[(8 * s + 4 + t) * 68 + pxb + g];
            const uint32_t a3 = sA[(8 * s + 4 + t) * 68 + pxb + g + 8];
#pragma unroll
            for (int ng = 0; ng < 3; ng++) {
                const uint32_t b0 = sB[(8 * ng + g) * 100 + 8 * s + t];
                const uint32_t b1 = sB[(8 * ng + g) * 100 + 8 * s + 4 + t];
                mma16816(dfr[ng], a0, a1, a2, a3, b0, b1);
            }
        }
        // store D frags: rows px, cols classes
        {
            const int px0 = pxb + g;
#pragma unroll
            for (int ng = 0; ng < 3; ng++) {
                *reinterpret_cast<float2*>(&slog[half][px0 * 26 + 8 * ng + 2 * t]) =
                    make_float2(dfr[ng][0], dfr[ng][1]);
                *reinterpret_cast<float2*>(&slog[half][(px0 + 8) * 26 + 8 * ng + 2 * t]) =
                    make_float2(dfr[ng][2], dfr[ng][3]);
            }
        }
        __syncthreads();

        // ---- softmax NLL: 64 threads, one pixel each; reset ssp after use ----
        if (tid < 64) {
            float l[KCLS];
#pragma unroll
            for (int k = 0; k < KCLS; k++)
                l[k] = slog[0][tid * 26 + k] + slog[1][tid * 26 + k];
            const float ssv = ssp[tid];
            ssp[tid] = 0.f;                 // ready for next chunk (ordered by bar)
            lsum += pix_loss(l, ssv, sM[tid]);
        }
    }

    // block reduction -> double atomic
#pragma unroll
    for (int o = 16; o; o >>= 1) lsum += __shfl_xor_sync(0xffffffffu, lsum, o);
    __shared__ float wsum[8];
    if ((tid & 31) == 0) wsum[tid >> 5] = lsum;
    __syncthreads();
    if (tid < 8) {
        float v = wsum[tid];
#pragma unroll
        for (int o = 4; o; o >>= 1) v += __shfl_xor_sync(0x000000ffu, v, o);
        if (tid == 0) atomicAdd(&g_loss, (double)v);
    }
}

// -------- launch 4: finalize --------
__global__ void k_fin(float* out) {
    int s = 0;
    for (int t = threadIdx.x; t < 1024; t += 256) s += g_cnt[t];
#pragma unroll
    for (int o = 16; o; o >>= 1) s += __shfl_xor_sync(0xffffffffu, s, o);
    __shared__ int ws[8];
    if ((threadIdx.x & 31) == 0) ws[threadIdx.x >> 5] = s;
    __syncthreads();
    if (threadIdx.x == 0) {
        int np = 0;
#pragma unroll
        for (int w = 0; w < 8; w++) np += ws[w];
        out[0] = (float)(g_loss / (double)(np > 0 ? np : 1));
    }
}

extern "C" void kernel_launch(void* const* d_in, const int* in_sizes, int n_in,
                              void* d_out, int out_size) {
    const float* feat = (const float*)d_in[0];
    const int*   gt   = (const int*)d_in[1];
    float*       out  = (float*)d_out;

    k_mask     <<<NPIX / (256 * 4), 256>>>(gt);
    k_zero     <<<5, 256>>>();
    k_proto_mma<<<592, 256>>>(feat);
    k_loss_mma <<<444, 256>>>(feat);
    k_fin      <<<1, 256>>>(out);
}

// round 13
// speedup vs baseline: 1.0273x; 1.0273x over previous
#include <cuda_runtime.h>
#include <cuda_bf16.h>
#include <math.h>
#include <stdint.h>

// ContrastLoss: feat [4,64,512,512] f32, gt [4,19,512,512] i32 -> scalar f32

#define NPIX   (4 * 262144)
#define HW     262144
#define KCLS   19
#define CCH    64
#define TAUF   0.07f
#define LOG2E  1.4426950408889634f
#define CH64   16384               // NPIX / 64 chunks

// -------- device scratch --------
__device__ float    g_k0[KCLS * CCH];
__device__ unsigned g_maskbuf[NPIX];
__device__ int      g_cnt[1024];
__device__ double   g_loss;

// ======== bf16 hi/lo pack: low16 = bf16(f), high16 = bf16(f - float(bf16(f))) ====
__device__ __forceinline__ uint32_t hilo(float f) {
    uint32_t h;
    asm("cvt.rn.bf16x2.f32 %0, %1, %2;" : "=r"(h) : "f"(0.f), "f"(f));
    const float hf = __uint_as_float(h << 16);
    const float lo = f - hf;
    uint32_t r;
    asm("cvt.rn.bf16x2.f32 %0, %1, %2;" : "=r"(r) : "f"(lo), "f"(f));
    return r;
}
// both halves = bf16(f)
__device__ __forceinline__ uint32_t bdup(float f) {
    uint32_t r;
    asm("cvt.rn.bf16x2.f32 %0, %1, %1;" : "=r"(r) : "f"(f));
    return r;
}

// ======== warp MMA m16n8k16 bf16 ========
__device__ __forceinline__ void mma16816(float* d, uint32_t a0, uint32_t a1,
                                         uint32_t a2, uint32_t a3,
                                         uint32_t b0, uint32_t b1) {
    asm volatile(
        "mma.sync.aligned.m16n8k16.row.col.f32.bf16.bf16.f32 "
        "{%0,%1,%2,%3}, {%4,%5,%6,%7}, {%8,%9}, {%0,%1,%2,%3};"
        : "+f"(d[0]), "+f"(d[1]), "+f"(d[2]), "+f"(d[3])
        : "r"(a0), "r"(a1), "r"(a2), "r"(a3), "r"(b0), "r"(b1));
}

// -------- launch 1: zero accumulators --------
__global__ void k_zero() {
    int t = blockIdx.x * 256 + threadIdx.x;
    if (t < KCLS * CCH) g_k0[t] = 0.f;
    if (t == 0) g_loss = 0.0;
}

// -------- launch 0: build 19-bit pixel masks + per-block pos counts --------
__global__ __launch_bounds__(256) void k_mask(const int* __restrict__ gt) {
    const int p4 = (blockIdx.x * 256 + threadIdx.x) * 4;   // 1024 blocks exactly
    const int b  = p4 >> 18;
    const int hw = p4 & (HW - 1);
    unsigned m0 = 0, m1 = 0, m2 = 0, m3 = 0;
#pragma unroll
    for (int k = 0; k < KCLS; k++) {
        const int4 g = *reinterpret_cast<const int4*>(
            gt + (size_t)(b * KCLS + k) * HW + hw);
        m0 |= (unsigned)(g.x == 1) << k;
        m1 |= (unsigned)(g.y == 1) << k;
        m2 |= (unsigned)(g.z == 1) << k;
        m3 |= (unsigned)(g.w == 1) << k;
    }
    *reinterpret_cast<uint4*>(&g_maskbuf[p4]) = make_uint4(m0, m1, m2, m3);
    int cnt = __popc(m0) + __popc(m1) + __popc(m2) + __popc(m3);
#pragma unroll
    for (int o = 16; o; o >>= 1) cnt += __shfl_xor_sync(0xffffffffu, cnt, o);
    __shared__ int sc[8];
    if ((threadIdx.x & 31) == 0) sc[threadIdx.x >> 5] = cnt;
    __syncthreads();
    if (threadIdx.x == 0) {
        int s = 0;
#pragma unroll
        for (int w = 0; w < 8; w++) s += sc[w];
        g_cnt[blockIdx.x] = s;
    }
}

// -------- launch 2: smem-staged HMMA prototype GEMM (validated R10) --------
__global__ __launch_bounds__(256, 4) void k_proto_mma(const float* __restrict__ feat) {
    __shared__ uint32_t sA[64 * 80];
    __shared__ uint32_t sM[64];
    __shared__ float    sk0[KCLS * CCH];

    const int tid  = threadIdx.x;
    const int w    = tid >> 5;
    const int lane = tid & 31;
    const int g    = lane >> 2;
    const int t    = lane & 3;
    const int chb  = (w & 3) * 16;
    const int hb   = (w >> 2) * 32;
    const int sc_hi = lane >> 4;
    const int sc_px = (lane & 15) * 4;

    for (int i = tid; i < KCLS * CCH; i += 256) sk0[i] = 0.f;

    float d0[4] = {0.f, 0.f, 0.f, 0.f};
    float d1[4] = {0.f, 0.f, 0.f, 0.f};
    float d2[4] = {0.f, 0.f, 0.f, 0.f};

    for (int chunk = blockIdx.x; chunk < CH64; chunk += gridDim.x) {
        const int P  = chunk * 64;
        const int b  = P >> 18;
        const int hw = P & (HW - 1);
        __syncthreads();

#pragma unroll
        for (int i = 0; i < 4; i++) {
            const int ch = w * 8 + 2 * i + sc_hi;
            const float4 f = *reinterpret_cast<const float4*>(
                feat + (size_t)(b * CCH + ch) * HW + hw + sc_px);
            const uint32_t h0 = hilo(f.x);
            const uint32_t h1 = hilo(f.y);
            const uint32_t h2 = hilo(f.z);
            const uint32_t h3 = hilo(f.w);
            const int word = ch * 80 + (sc_px ^ ((ch & 3) << 3));
            *reinterpret_cast<uint4*>(&sA[word]) = make_uint4(h0, h1, h2, h3);
        }
        if (tid < 16)
            *reinterpret_cast<uint4*>(&sM[tid * 4]) =
                *reinterpret_cast<const uint4*>(&g_maskbuf[P + tid * 4]);
        __syncthreads();

#pragma unroll
        for (int s = 0; s < 4; s++) {
            const int px = hb + 8 * s + 2 * t;
            const int sw = px ^ ((g & 3) << 3);
            const uint2 A0 = *reinterpret_cast<const uint2*>(&sA[(chb + g) * 80 + sw]);
            const uint2 A1 = *reinterpret_cast<const uint2*>(&sA[(chb + g + 8) * 80 + sw]);
            const uint2 M  = *reinterpret_cast<const uint2*>(&sM[px]);
            {
                const uint32_t b0 = ((M.x >> g) & 1u) * 0x3F803F80u;
                const uint32_t b1 = ((M.y >> g) & 1u) * 0x3F803F80u;
                mma16816(d0, A0.x, A1.x, A0.y, A1.y, b0, b1);
            }
            {
                const uint32_t b0 = ((M.x >> (8 + g)) & 1u) * 0x3F803F80u;
                const uint32_t b1 = ((M.y >> (8 + g)) & 1u) * 0x3F803F80u;
                mma16816(d1, A0.x, A1.x, A0.y, A1.y, b0, b1);
            }
            {
                const uint32_t b0 = ((M.x >> (16 + g)) & 1u) * 0x3F803F80u;
                const uint32_t b1 = ((M.y >> (16 + g)) & 1u) * 0x3F803F80u;
                mma16816(d2, A0.x, A1.x, A0.y, A1.y, b0, b1);
            }
        }
    }

    __syncthreads();
    {
        const int c0 = chb + g;
        const int c1 = chb + g + 8;
        const int k0c = 2 * t, k1c = 2 * t + 1;
        atomicAdd(&sk0[(k0c)     * CCH + c0], d0[0]);
        atomicAdd(&sk0[(k1c)     * CCH + c0], d0[1]);
        atomicAdd(&sk0[(k0c)     * CCH + c1], d0[2]);
        atomicAdd(&sk0[(k1c)     * CCH + c1], d0[3]);
        atomicAdd(&sk0[(8 + k0c) * CCH + c0], d1[0]);
        atomicAdd(&sk0[(8 + k1c) * CCH + c0], d1[1]);
        atomicAdd(&sk0[(8 + k0c) * CCH + c1], d1[2]);
        atomicAdd(&sk0[(8 + k1c) * CCH + c1], d1[3]);
        if (16 + k0c < KCLS) {
            atomicAdd(&sk0[(16 + k0c) * CCH + c0], d2[0]);
            atomicAdd(&sk0[(16 + k0c) * CCH + c1], d2[2]);
        }
        if (16 + k1c < KCLS) {
            atomicAdd(&sk0[(16 + k1c) * CCH + c0], d2[1]);
            atomicAdd(&sk0[(16 + k1c) * CCH + c1], d2[3]);
        }
    }
    __syncthreads();
    for (int i = tid; i < KCLS * CCH; i += 256) atomicAdd(&g_k0[i], sk0[i]);
}

// -------- per-pixel softmax/NLL (tau pre-folded into prototypes) --------
__device__ __forceinline__ float pix_loss(const float* __restrict__ l,
                                          float ssum, unsigned m) {
    const float sc = 1.f / fmaxf(sqrtf(ssum), 1e-12f);
    float v[KCLS];
    float mx = -1e30f;
#pragma unroll
    for (int k = 0; k < KCLS; k++) {
        v[k] = l[k] * sc;
        mx = fmaxf(mx, v[k]);
    }
    float se = 0.f, sl = 0.f;
#pragma unroll
    for (int k = 0; k < KCLS; k++) {
        se += exp2f((v[k] - mx) * LOG2E);
        if (m & (1u << k)) sl += v[k];
    }
    return (float)__popc(m) * (mx + logf(se)) - sl;
}

// -------- launch 3: HMMA logits + softmax NLL (PROFILED SLOT) --------
// K = 192 u16 slots: word p (0..63): A=(fhi_p, flo_p) B=(phi_p, phi_p);
// word 64+j: A=(fhi_2j, fhi_2j+1) B=(plo_2j, plo_2j+1).
// R13: sA stride 72 (A-load banks 8t+g all-distinct, conflict-free) and
// B fragments hoisted to 36 regs/warp, loaded ONCE (B is chunk-invariant).
__global__ __launch_bounds__(256, 2) void k_loss_mma(const float* __restrict__ feat) {
    __shared__ uint32_t sA[96 * 72];        // 27.6 KB
    __shared__ uint32_t sB[24 * 100];       // 9.6 KB (preamble only)
    __shared__ float    slog[2][64 * 26];   // 13.3 KB
    __shared__ float    ssp[64];
    __shared__ uint32_t sM[64];
    __shared__ float    sinv[32];

    const int tid  = threadIdx.x;
    const int w    = tid >> 5;
    const int lane = tid & 31;
    const int g    = lane >> 2;
    const int t    = lane & 3;
    const int sc_hi = lane >> 4;
    const int sc_px = (lane & 15) * 4;
    const int half = w >> 2;
    const int pxb  = (w & 3) * 16;

    // ---- preamble: prototype norms, build sB, zero ssp ----
    if (tid < KCLS) {
        float s = 0.f;
#pragma unroll
        for (int c = 0; c < CCH; c++) {
            const float v = g_k0[tid * CCH + c];
            s = fmaf(v, v, s);
        }
        sinv[tid] = 1.f / (fmaxf(sqrtf(s), 1e-12f) * TAUF);
    }
    if (tid < 64) ssp[tid] = 0.f;
    __syncthreads();
    for (int idx = tid; idx < 24 * CCH; idx += 256) {
        const int k = idx >> 6;
        const int c = idx & 63;
        const float p = (k < KCLS) ? g_k0[k * CCH + c] * sinv[k] : 0.f;
        const uint32_t wph = bdup(p);
        sB[k * 100 + c] = wph;
        const float phf = __uint_as_float(wph << 16);
        const uint32_t wpl = bdup(p - phf);
        reinterpret_cast<uint16_t*>(&sB[k * 100 + 64 + (c >> 1)])[c & 1] =
            (uint16_t)(wpl & 0xFFFFu);
    }
    __syncthreads();

    // ---- hoist B fragments into registers: warp's 6 K-steps x 3 ng x 2 ----
    uint32_t Breg[6][3][2];
#pragma unroll
    for (int s6 = 0; s6 < 6; s6++) {
        const int s = half * 6 + s6;
#pragma unroll
        for (int ng = 0; ng < 3; ng++) {
            Breg[s6][ng][0] = sB[(8 * ng + g) * 100 + 8 * s + t];
            Breg[s6][ng][1] = sB[(8 * ng + g) * 100 + 8 * s + 4 + t];
        }
    }

    float lsum = 0.f;
    for (int chunk = blockIdx.x; chunk < CH64; chunk += gridDim.x) {
        const int P  = chunk * 64;
        const int b  = P >> 18;
        const int hw = P & (HW - 1);
        __syncthreads();   // bar: prev softmax (incl. ssp reset) done

        // ---- stage: feat -> sA (stride 72), ss partials, masks ----
        if (tid < 16)
            *reinterpret_cast<uint4*>(&sM[tid * 4]) =
                *reinterpret_cast<const uint4*>(&g_maskbuf[P + tid * 4]);
        float ss4[4] = {0.f, 0.f, 0.f, 0.f};
#pragma unroll
        for (int i = 0; i < 4; i++) {
            const int ch = w * 8 + 2 * i + sc_hi;
            const float4 f = *reinterpret_cast<const float4*>(
                feat + (size_t)(b * CCH + ch) * HW + hw + sc_px);
            uint32_t hv0 = hilo(f.x), hv1 = hilo(f.y), hv2 = hilo(f.z), hv3 = hilo(f.w);
            *reinterpret_cast<uint4*>(&sA[ch * 72 + sc_px]) =
                make_uint4(hv0, hv1, hv2, hv3);
            ss4[0] = fmaf(f.x, f.x, ss4[0]);
            ss4[1] = fmaf(f.y, f.y, ss4[1]);
            ss4[2] = fmaf(f.z, f.z, ss4[2]);
            ss4[3] = fmaf(f.w, f.w, ss4[3]);
            // fhi pair words (row 64 + w*4 + i): (fhi_even, fhi_odd)
            const uint32_t p0 = __shfl_xor_sync(0xffffffffu, hv0, 16);
            const uint32_t p1 = __shfl_xor_sync(0xffffffffu, hv1, 16);
            const uint32_t p2 = __shfl_xor_sync(0xffffffffu, hv2, 16);
            const uint32_t p3 = __shfl_xor_sync(0xffffffffu, hv3, 16);
            if (sc_hi == 0) {
                const int r2 = (64 + w * 4 + i) * 72 + sc_px;
                *reinterpret_cast<uint4*>(&sA[r2]) = make_uint4(
                    (hv0 & 0xFFFFu) | (p0 << 16),
                    (hv1 & 0xFFFFu) | (p1 << 16),
                    (hv2 & 0xFFFFu) | (p2 << 16),
                    (hv3 & 0xFFFFu) | (p3 << 16));
            }
        }
#pragma unroll
        for (int j = 0; j < 4; j++)
            ss4[j] += __shfl_xor_sync(0xffffffffu, ss4[j], 16);
        if (sc_hi == 0) {
#pragma unroll
            for (int j = 0; j < 4; j++)
                atomicAdd(&ssp[sc_px + j], ss4[j]);
        }
        __syncthreads();

        // ---- MMA: 6 K-steps x 3 n-groups, B from registers ----
        float dfr[3][4];
#pragma unroll
        for (int n = 0; n < 3; n++)
#pragma unroll
            for (int q = 0; q < 4; q++) dfr[n][q] = 0.f;
#pragma unroll
        for (int s6 = 0; s6 < 6; s6++) {
            const int s = half * 6 + s6;
            const uint32_t a0 = sA[(8 * s + t) * 72 + pxb + g];
            const uint32_t a1 = sA[(8 * s + t) * 72 + pxb + g + 8];
            const uint32_t a2 = sA[(8 * s + 4 + t) * 72 + pxb + g];
            const uint32_t a3 = sA[(8 * s + 4 + t) * 72 + pxb + g + 8];
#pragma unroll
            for (int ng = 0; ng < 3; ng++)
                mma16816(dfr[ng], a0, a1, a2, a3,
                         Breg[s6][ng][0], Breg[s6][ng][1]);
        }
        // store D frags: rows px, cols classes
        {
            const int px0 = pxb + g;
#pragma unroll
            for (int ng = 0; ng < 3; ng++) {
                *reinterpret_cast<float2*>(&slog[half][px0 * 26 + 8 * ng + 2 * t]) =
                    make_float2(dfr[ng][0], dfr[ng][1]);
                *reinterpret_cast<float2*>(&slog[half][(px0 + 8) * 26 + 8 * ng + 2 * t]) =
                    make_float2(dfr[ng][2], dfr[ng][3]);
            }
        }
        __syncthreads();

        // ---- softmax NLL: 64 threads, one pixel each; reset ssp after use ----
        if (tid < 64) {
            float l[KCLS];
#pragma unroll
            for (int k = 0; k < KCLS; k++)
                l[k] = slog[0][tid * 26 + k] + slog[1][tid * 26 + k];
            const float ssv = ssp[tid];
            ssp[tid] = 0.f;                 // ordered by loop-top barrier
            lsum += pix_loss(l, ssv, sM[tid]);
        }
    }

    // block reduction -> double atomic
#pragma unroll
    for (int o = 16; o; o >>= 1) lsum += __shfl_xor_sync(0xffffffffu, lsum, o);
    __shared__ float wsum[8];
    if ((tid & 31) == 0) wsum[tid >> 5] = lsum;
    __syncthreads();
    if (tid < 8) {
        float v = wsum[tid];
#pragma unroll
        for (int o = 4; o; o >>= 1) v += __shfl_xor_sync(0x000000ffu, v, o);
        if (tid == 0) atomicAdd(&g_loss, (double)v);
    }
}

// -------- launch 4: finalize --------
__global__ void k_fin(float* out) {
    int s = 0;
    for (int t = threadIdx.x; t < 1024; t += 256) s += g_cnt[t];
#pragma unroll
    for (int o = 16; o; o >>= 1) s += __shfl_xor_sync(0xffffffffu, s, o);
    __shared__ int ws[8];
    if ((threadIdx.x & 31) == 0) ws[threadIdx.x >> 5] = s;
    __syncthreads();
    if (threadIdx.x == 0) {
        int np = 0;
#pragma unroll
        for (int w = 0; w < 8; w++) np += ws[w];
        out[0] = (float)(g_loss / (double)(np > 0 ? np : 1));
    }
}

extern "C" void kernel_launch(void* const* d_in, const int* in_sizes, int n_in,
                              void* d_out, int out_size) {
    const float* feat = (const float*)d_in[0];
    const int*   gt   = (const int*)d_in[1];
    float*       out  = (float*)d_out;

    k_mask     <<<NPIX / (256 * 4), 256>>>(gt);
    k_zero     <<<5, 256>>>();
    k_proto_mma<<<592, 256>>>(feat);
    k_loss_mma <<<296, 256>>>(feat);
    k_fin      <<<1, 256>>>(out);
}

// round 14
// speedup vs baseline: 1.0713x; 1.0428x over previous
#include <cuda_runtime.h>
#include <cuda_bf16.h>
#include <math.h>
#include <stdint.h>

// ContrastLoss: feat [4,64,512,512] f32, gt [4,19,512,512] i32 -> scalar f32

#define NPIX   (4 * 262144)
#define HW     262144
#define KCLS   19
#define CCH    64
#define TAUF   0.07f
#define LOG2E  1.4426950408889634f
#define CH64   16384               // NPIX / 64 chunks

// -------- device scratch --------
__device__ float    g_k0[KCLS * CCH];
__device__ unsigned g_maskbuf[NPIX];
__device__ int      g_cnt[1024];
__device__ double   g_loss;

// ======== f32x2 helpers ========
__device__ __forceinline__ unsigned long long pack2(float a, float b) {
    unsigned long long r;
    asm("mov.b64 %0, {%1, %2};" : "=l"(r) : "f"(a), "f"(b));
    return r;
}
__device__ __forceinline__ void unpack2(unsigned long long v, float& a, float& b) {
    asm("mov.b64 {%0, %1}, %2;" : "=f"(a), "=f"(b) : "l"(v));
}
__device__ __forceinline__ void ffma2(unsigned long long& d, unsigned long long a,
                                      unsigned long long b) {
    asm("fma.rn.f32x2 %0, %1, %2, %0;" : "+l"(d) : "l"(a), "l"(b));
}

// ======== bf16 hi/lo pack: low16 = bf16(f), high16 = bf16(f - float(bf16(f))) ====
__device__ __forceinline__ uint32_t hilo(float f) {
    uint32_t h;
    asm("cvt.rn.bf16x2.f32 %0, %1, %2;" : "=r"(h) : "f"(0.f), "f"(f));
    const float hf = __uint_as_float(h << 16);
    const float lo = f - hf;
    uint32_t r;
    asm("cvt.rn.bf16x2.f32 %0, %1, %2;" : "=r"(r) : "f"(lo), "f"(f));
    return r;
}

// ======== warp MMA m16n8k16 bf16 ========
__device__ __forceinline__ void mma16816(float* d, uint32_t a0, uint32_t a1,
                                         uint32_t a2, uint32_t a3,
                                         uint32_t b0, uint32_t b1) {
    asm volatile(
        "mma.sync.aligned.m16n8k16.row.col.f32.bf16.bf16.f32 "
        "{%0,%1,%2,%3}, {%4,%5,%6,%7}, {%8,%9}, {%0,%1,%2,%3};"
        : "+f"(d[0]), "+f"(d[1]), "+f"(d[2]), "+f"(d[3])
        : "r"(a0), "r"(a1), "r"(a2), "r"(a3), "r"(b0), "r"(b1));
}

// -------- launch 1: zero accumulators --------
__global__ void k_zero() {
    int t = blockIdx.x * 256 + threadIdx.x;
    if (t < KCLS * CCH) g_k0[t] = 0.f;
    if (t == 0) g_loss = 0.0;
}

// -------- launch 0: build 19-bit pixel masks + per-block pos counts --------
__global__ __launch_bounds__(256) void k_mask(const int* __restrict__ gt) {
    const int p4 = (blockIdx.x * 256 + threadIdx.x) * 4;   // 1024 blocks exactly
    const int b  = p4 >> 18;
    const int hw = p4 & (HW - 1);
    unsigned m0 = 0, m1 = 0, m2 = 0, m3 = 0;
#pragma unroll
    for (int k = 0; k < KCLS; k++) {
        const int4 g = *reinterpret_cast<const int4*>(
            gt + (size_t)(b * KCLS + k) * HW + hw);
        m0 |= (unsigned)(g.x == 1) << k;
        m1 |= (unsigned)(g.y == 1) << k;
        m2 |= (unsigned)(g.z == 1) << k;
        m3 |= (unsigned)(g.w == 1) << k;
    }
    *reinterpret_cast<uint4*>(&g_maskbuf[p4]) = make_uint4(m0, m1, m2, m3);
    int cnt = __popc(m0) + __popc(m1) + __popc(m2) + __popc(m3);
#pragma unroll
    for (int o = 16; o; o >>= 1) cnt += __shfl_xor_sync(0xffffffffu, cnt, o);
    __shared__ int sc[8];
    if ((threadIdx.x & 31) == 0) sc[threadIdx.x >> 5] = cnt;
    __syncthreads();
    if (threadIdx.x == 0) {
        int s = 0;
#pragma unroll
        for (int w = 0; w < 8; w++) s += sc[w];
        g_cnt[blockIdx.x] = s;
    }
}

// -------- launch 2: smem-staged HMMA prototype GEMM (validated R10, 58.7us) ----
__global__ __launch_bounds__(256, 4) void k_proto_mma(const float* __restrict__ feat) {
    __shared__ uint32_t sA[64 * 80];
    __shared__ uint32_t sM[64];
    __shared__ float    sk0[KCLS * CCH];

    const int tid  = threadIdx.x;
    const int w    = tid >> 5;
    const int lane = tid & 31;
    const int g    = lane >> 2;
    const int t    = lane & 3;
    const int chb  = (w & 3) * 16;
    const int hb   = (w >> 2) * 32;
    const int sc_hi = lane >> 4;
    const int sc_px = (lane & 15) * 4;

    for (int i = tid; i < KCLS * CCH; i += 256) sk0[i] = 0.f;

    float d0[4] = {0.f, 0.f, 0.f, 0.f};
    float d1[4] = {0.f, 0.f, 0.f, 0.f};
    float d2[4] = {0.f, 0.f, 0.f, 0.f};

    for (int chunk = blockIdx.x; chunk < CH64; chunk += gridDim.x) {
        const int P  = chunk * 64;
        const int b  = P >> 18;
        const int hw = P & (HW - 1);
        __syncthreads();

#pragma unroll
        for (int i = 0; i < 4; i++) {
            const int ch = w * 8 + 2 * i + sc_hi;
            const float4 f = *reinterpret_cast<const float4*>(
                feat + (size_t)(b * CCH + ch) * HW + hw + sc_px);
            const uint32_t h0 = hilo(f.x);
            const uint32_t h1 = hilo(f.y);
            const uint32_t h2 = hilo(f.z);
            const uint32_t h3 = hilo(f.w);
            const int word = ch * 80 + (sc_px ^ ((ch & 3) << 3));
            *reinterpret_cast<uint4*>(&sA[word]) = make_uint4(h0, h1, h2, h3);
        }
        if (tid < 16)
            *reinterpret_cast<uint4*>(&sM[tid * 4]) =
                *reinterpret_cast<const uint4*>(&g_maskbuf[P + tid * 4]);
        __syncthreads();

#pragma unroll
        for (int s = 0; s < 4; s++) {
            const int px = hb + 8 * s + 2 * t;
            const int sw = px ^ ((g & 3) << 3);
            const uint2 A0 = *reinterpret_cast<const uint2*>(&sA[(chb + g) * 80 + sw]);
            const uint2 A1 = *reinterpret_cast<const uint2*>(&sA[(chb + g + 8) * 80 + sw]);
            const uint2 M  = *reinterpret_cast<const uint2*>(&sM[px]);
            {
                const uint32_t b0 = ((M.x >> g) & 1u) * 0x3F803F80u;
                const uint32_t b1 = ((M.y >> g) & 1u) * 0x3F803F80u;
                mma16816(d0, A0.x, A1.x, A0.y, A1.y, b0, b1);
            }
            {
                const uint32_t b0 = ((M.x >> (8 + g)) & 1u) * 0x3F803F80u;
                const uint32_t b1 = ((M.y >> (8 + g)) & 1u) * 0x3F803F80u;
                mma16816(d1, A0.x, A1.x, A0.y, A1.y, b0, b1);
            }
            {
                const uint32_t b0 = ((M.x >> (16 + g)) & 1u) * 0x3F803F80u;
                const uint32_t b1 = ((M.y >> (16 + g)) & 1u) * 0x3F803F80u;
                mma16816(d2, A0.x, A1.x, A0.y, A1.y, b0, b1);
            }
        }
    }

    __syncthreads();
    {
        const int c0 = chb + g;
        const int c1 = chb + g + 8;
        const int k0c = 2 * t, k1c = 2 * t + 1;
        atomicAdd(&sk0[(k0c)     * CCH + c0], d0[0]);
        atomicAdd(&sk0[(k1c)     * CCH + c0], d0[1]);
        atomicAdd(&sk0[(k0c)     * CCH + c1], d0[2]);
        atomicAdd(&sk0[(k1c)     * CCH + c1], d0[3]);
        atomicAdd(&sk0[(8 + k0c) * CCH + c0], d1[0]);
        atomicAdd(&sk0[(8 + k1c) * CCH + c0], d1[1]);
        atomicAdd(&sk0[(8 + k0c) * CCH + c1], d1[2]);
        atomicAdd(&sk0[(8 + k1c) * CCH + c1], d1[3]);
        if (16 + k0c < KCLS) {
            atomicAdd(&sk0[(16 + k0c) * CCH + c0], d2[0]);
            atomicAdd(&sk0[(16 + k0c) * CCH + c1], d2[2]);
        }
        if (16 + k1c < KCLS) {
            atomicAdd(&sk0[(16 + k1c) * CCH + c0], d2[1]);
            atomicAdd(&sk0[(16 + k1c) * CCH + c1], d2[3]);
        }
    }
    __syncthreads();
    for (int i = tid; i < KCLS * CCH; i += 256) atomicAdd(&g_k0[i], sk0[i]);
}

// -------- per-pixel softmax/NLL (tau pre-folded into prototypes) --------
__device__ __forceinline__ float pix_loss(const float* __restrict__ l,
                                          float ssum, unsigned m) {
    const float sc = 1.f / fmaxf(sqrtf(ssum), 1e-12f);
    float v[KCLS];
    float mx = -1e30f;
#pragma unroll
    for (int k = 0; k < KCLS; k++) {
        v[k] = l[k] * sc;
        mx = fmaxf(mx, v[k]);
    }
    float se = 0.f, sl = 0.f;
#pragma unroll
    for (int k = 0; k < KCLS; k++) {
        se += exp2f((v[k] - mx) * LOG2E);
        if (m & (1u << k)) sl += v[k];
    }
    return (float)__popc(m) * (mx + logf(se)) - sl;
}

// -------- launch 3: fp32 logits + softmax NLL, 2 px/thread (PROFILED) --------
// R14: 2 px/thread (19 u64 accs) at launch_bounds(256,3) -> 24 warps/SM for
// latency hiding (R3 profile showed issue=38% at occ=22.8% with 4px/128regs).
__global__ __launch_bounds__(256, 3) void k_loss(const float* __restrict__ feat) {
    __shared__ unsigned long long sknd[KCLS * CCH];   // (kn/tau, kn/tau) duplicated
    __shared__ float sinv[KCLS];
    if (threadIdx.x < KCLS) {
        float s = 0.f;
#pragma unroll
        for (int c = 0; c < CCH; c++) {
            const float v = g_k0[threadIdx.x * CCH + c];
            s = fmaf(v, v, s);
        }
        sinv[threadIdx.x] = 1.f / (fmaxf(sqrtf(s), 1e-12f) * TAUF);
    }
    __syncthreads();
    for (int t = threadIdx.x; t < KCLS * CCH; t += 256) {
        const float v = g_k0[t] * sinv[t >> 6];
        sknd[t] = pack2(v, v);
    }
    __syncthreads();

    const int p2 = (blockIdx.x * 256 + threadIdx.x) * 2;   // 2048 blocks exactly
    const uint2 m2 = *reinterpret_cast<const uint2*>(&g_maskbuf[p2]);
    const int   b  = p2 >> 18;
    const int   hw = p2 & (HW - 1);
    const float* fb = feat + (size_t)(b * CCH) * HW + hw;

    unsigned long long acc[KCLS];
#pragma unroll
    for (int k = 0; k < KCLS; k++) acc[k] = 0ull;
    unsigned long long ss = 0ull;

#pragma unroll 4
    for (int c2 = 0; c2 < 32; c2++) {
        const unsigned long long F0 =
            *reinterpret_cast<const unsigned long long*>(fb + (size_t)(2 * c2) * HW);
        const unsigned long long F1 =
            *reinterpret_cast<const unsigned long long*>(fb + (size_t)(2 * c2 + 1) * HW);
        ffma2(ss, F0, F0);
        ffma2(ss, F1, F1);
#pragma unroll
        for (int k = 0; k < KCLS; k++) {
            const ulonglong2 kd =
                *reinterpret_cast<const ulonglong2*>(&sknd[k * CCH + 2 * c2]);
            ffma2(acc[k], F0, kd.x);
            ffma2(acc[k], F1, kd.y);
        }
    }

    float s0, s1;
    unpack2(ss, s0, s1);
    float l0[KCLS], l1[KCLS];
#pragma unroll
    for (int k = 0; k < KCLS; k++) unpack2(acc[k], l0[k], l1[k]);

    float lsum = pix_loss(l0, s0, m2.x) + pix_loss(l1, s1, m2.y);

    // block reduction -> double atomic
#pragma unroll
    for (int o = 16; o; o >>= 1) lsum += __shfl_xor_sync(0xffffffffu, lsum, o);
    __shared__ float wsum[8];
    if ((threadIdx.x & 31) == 0) wsum[threadIdx.x >> 5] = lsum;
    __syncthreads();
    if (threadIdx.x < 8) {
        float v = wsum[threadIdx.x];
#pragma unroll
        for (int o = 4; o; o >>= 1) v += __shfl_xor_sync(0x000000ffu, v, o);
        if (threadIdx.x == 0) atomicAdd(&g_loss, (double)v);
    }
}

// -------- launch 4: finalize --------
__global__ void k_fin(float* out) {
    int s = 0;
    for (int t = threadIdx.x; t < 1024; t += 256) s += g_cnt[t];
#pragma unroll
    for (int o = 16; o; o >>= 1) s += __shfl_xor_sync(0xffffffffu, s, o);
    __shared__ int ws[8];
    if ((threadIdx.x & 31) == 0) ws[threadIdx.x >> 5] = s;
    __syncthreads();
    if (threadIdx.x == 0) {
        int np = 0;
#pragma unroll
        for (int w = 0; w < 8; w++) np += ws[w];
        out[0] = (float)(g_loss / (double)(np > 0 ? np : 1));
    }
}

extern "C" void kernel_launch(void* const* d_in, const int* in_sizes, int n_in,
                              void* d_out, int out_size) {
    const float* feat = (const float*)d_in[0];
    const int*   gt   = (const int*)d_in[1];
    float*       out  = (float*)d_out;

    k_mask     <<<NPIX / (256 * 4), 256>>>(gt);
    k_zero     <<<5, 256>>>();
    k_proto_mma<<<592, 256>>>(feat);
    k_loss     <<<NPIX / (256 * 2), 256>>>(feat);
    k_fin      <<<1, 256>>>(out);
}

// round 15
// speedup vs baseline: 1.1778x; 1.0994x over previous
#include <cuda_runtime.h>
#include <cuda_bf16.h>
#include <math.h>
#include <stdint.h>

// ContrastLoss: feat [4,64,512,512] f32, gt [4,19,512,512] i32 -> scalar f32

#define NPIX   (4 * 262144)
#define HW     262144
#define KCLS   19
#define CCH    64
#define TAUF   0.07f
#define LOG2E  1.4426950408889634f
#define CH64   16384               // NPIX / 64 chunks

// -------- device scratch --------
__device__ float    g_k0[KCLS * CCH];
__device__ unsigned g_maskbuf[NPIX];
__device__ int      g_cnt[1024];
__device__ double   g_loss;

// ======== f32x2 helpers ========
__device__ __forceinline__ unsigned long long pack2(float a, float b) {
    unsigned long long r;
    asm("mov.b64 %0, {%1, %2};" : "=l"(r) : "f"(a), "f"(b));
    return r;
}
__device__ __forceinline__ void unpack2(unsigned long long v, float& a, float& b) {
    asm("mov.b64 {%0, %1}, %2;" : "=f"(a), "=f"(b) : "l"(v));
}
__device__ __forceinline__ void ffma2(unsigned long long& d, unsigned long long a,
                                      unsigned long long b) {
    asm("fma.rn.f32x2 %0, %1, %2, %0;" : "+l"(d) : "l"(a), "l"(b));
}

// ======== bf16 hi/lo pack: low16 = bf16(f), high16 = bf16(f - float(bf16(f))) ====
__device__ __forceinline__ uint32_t hilo(float f) {
    uint32_t h;
    asm("cvt.rn.bf16x2.f32 %0, %1, %2;" : "=r"(h) : "f"(0.f), "f"(f));
    const float hf = __uint_as_float(h << 16);
    const float lo = f - hf;
    uint32_t r;
    asm("cvt.rn.bf16x2.f32 %0, %1, %2;" : "=r"(r) : "f"(lo), "f"(f));
    return r;
}

// ======== warp MMA m16n8k16 bf16 ========
__device__ __forceinline__ void mma16816(float* d, uint32_t a0, uint32_t a1,
                                         uint32_t a2, uint32_t a3,
                                         uint32_t b0, uint32_t b1) {
    asm volatile(
        "mma.sync.aligned.m16n8k16.row.col.f32.bf16.bf16.f32 "
        "{%0,%1,%2,%3}, {%4,%5,%6,%7}, {%8,%9}, {%0,%1,%2,%3};"
        : "+f"(d[0]), "+f"(d[1]), "+f"(d[2]), "+f"(d[3])
        : "r"(a0), "r"(a1), "r"(a2), "r"(a3), "r"(b0), "r"(b1));
}

// -------- launch 1: zero accumulators --------
__global__ void k_zero() {
    int t = blockIdx.x * 256 + threadIdx.x;
    if (t < KCLS * CCH) g_k0[t] = 0.f;
    if (t == 0) g_loss = 0.0;
}

// -------- launch 0: build 19-bit pixel masks + per-block pos counts --------
__global__ __launch_bounds__(256) void k_mask(const int* __restrict__ gt) {
    const int p4 = (blockIdx.x * 256 + threadIdx.x) * 4;   // 1024 blocks exactly
    const int b  = p4 >> 18;
    const int hw = p4 & (HW - 1);
    unsigned m0 = 0, m1 = 0, m2 = 0, m3 = 0;
#pragma unroll
    for (int k = 0; k < KCLS; k++) {
        const int4 g = *reinterpret_cast<const int4*>(
            gt + (size_t)(b * KCLS + k) * HW + hw);
        m0 |= (unsigned)(g.x == 1) << k;
        m1 |= (unsigned)(g.y == 1) << k;
        m2 |= (unsigned)(g.z == 1) << k;
        m3 |= (unsigned)(g.w == 1) << k;
    }
    *reinterpret_cast<uint4*>(&g_maskbuf[p4]) = make_uint4(m0, m1, m2, m3);
    int cnt = __popc(m0) + __popc(m1) + __popc(m2) + __popc(m3);
#pragma unroll
    for (int o = 16; o; o >>= 1) cnt += __shfl_xor_sync(0xffffffffu, cnt, o);
    __shared__ int sc[8];
    if ((threadIdx.x & 31) == 0) sc[threadIdx.x >> 5] = cnt;
    __syncthreads();
    if (threadIdx.x == 0) {
        int s = 0;
#pragma unroll
        for (int w = 0; w < 8; w++) s += sc[w];
        g_cnt[blockIdx.x] = s;
    }
}

// -------- launch 2: smem-staged HMMA prototype GEMM (validated R10, 58.7us) ----
__global__ __launch_bounds__(256, 4) void k_proto_mma(const float* __restrict__ feat) {
    __shared__ uint32_t sA[64 * 80];
    __shared__ uint32_t sM[64];
    __shared__ float    sk0[KCLS * CCH];

    const int tid  = threadIdx.x;
    const int w    = tid >> 5;
    const int lane = tid & 31;
    const int g    = lane >> 2;
    const int t    = lane & 3;
    const int chb  = (w & 3) * 16;
    const int hb   = (w >> 2) * 32;
    const int sc_hi = lane >> 4;
    const int sc_px = (lane & 15) * 4;

    for (int i = tid; i < KCLS * CCH; i += 256) sk0[i] = 0.f;

    float d0[4] = {0.f, 0.f, 0.f, 0.f};
    float d1[4] = {0.f, 0.f, 0.f, 0.f};
    float d2[4] = {0.f, 0.f, 0.f, 0.f};

    for (int chunk = blockIdx.x; chunk < CH64; chunk += gridDim.x) {
        const int P  = chunk * 64;
        const int b  = P >> 18;
        const int hw = P & (HW - 1);
        __syncthreads();

#pragma unroll
        for (int i = 0; i < 4; i++) {
            const int ch = w * 8 + 2 * i + sc_hi;
            const float4 f = *reinterpret_cast<const float4*>(
                feat + (size_t)(b * CCH + ch) * HW + hw + sc_px);
            const uint32_t h0 = hilo(f.x);
            const uint32_t h1 = hilo(f.y);
            const uint32_t h2 = hilo(f.z);
            const uint32_t h3 = hilo(f.w);
            const int word = ch * 80 + (sc_px ^ ((ch & 3) << 3));
            *reinterpret_cast<uint4*>(&sA[word]) = make_uint4(h0, h1, h2, h3);
        }
        if (tid < 16)
            *reinterpret_cast<uint4*>(&sM[tid * 4]) =
                *reinterpret_cast<const uint4*>(&g_maskbuf[P + tid * 4]);
        __syncthreads();

#pragma unroll
        for (int s = 0; s < 4; s++) {
            const int px = hb + 8 * s + 2 * t;
            const int sw = px ^ ((g & 3) << 3);
            const uint2 A0 = *reinterpret_cast<const uint2*>(&sA[(chb + g) * 80 + sw]);
            const uint2 A1 = *reinterpret_cast<const uint2*>(&sA[(chb + g + 8) * 80 + sw]);
            const uint2 M  = *reinterpret_cast<const uint2*>(&sM[px]);
            {
                const uint32_t b0 = ((M.x >> g) & 1u) * 0x3F803F80u;
                const uint32_t b1 = ((M.y >> g) & 1u) * 0x3F803F80u;
                mma16816(d0, A0.x, A1.x, A0.y, A1.y, b0, b1);
            }
            {
                const uint32_t b0 = ((M.x >> (8 + g)) & 1u) * 0x3F803F80u;
                const uint32_t b1 = ((M.y >> (8 + g)) & 1u) * 0x3F803F80u;
                mma16816(d1, A0.x, A1.x, A0.y, A1.y, b0, b1);
            }
            {
                const uint32_t b0 = ((M.x >> (16 + g)) & 1u) * 0x3F803F80u;
                const uint32_t b1 = ((M.y >> (16 + g)) & 1u) * 0x3F803F80u;
                mma16816(d2, A0.x, A1.x, A0.y, A1.y, b0, b1);
            }
        }
    }

    __syncthreads();
    {
        const int c0 = chb + g;
        const int c1 = chb + g + 8;
        const int k0c = 2 * t, k1c = 2 * t + 1;
        atomicAdd(&sk0[(k0c)     * CCH + c0], d0[0]);
        atomicAdd(&sk0[(k1c)     * CCH + c0], d0[1]);
        atomicAdd(&sk0[(k0c)     * CCH + c1], d0[2]);
        atomicAdd(&sk0[(k1c)     * CCH + c1], d0[3]);
        atomicAdd(&sk0[(8 + k0c) * CCH + c0], d1[0]);
        atomicAdd(&sk0[(8 + k1c) * CCH + c0], d1[1]);
        atomicAdd(&sk0[(8 + k0c) * CCH + c1], d1[2]);
        atomicAdd(&sk0[(8 + k1c) * CCH + c1], d1[3]);
        if (16 + k0c < KCLS) {
            atomicAdd(&sk0[(16 + k0c) * CCH + c0], d2[0]);
            atomicAdd(&sk0[(16 + k0c) * CCH + c1], d2[2]);
        }
        if (16 + k1c < KCLS) {
            atomicAdd(&sk0[(16 + k1c) * CCH + c0], d2[1]);
            atomicAdd(&sk0[(16 + k1c) * CCH + c1], d2[3]);
        }
    }
    __syncthreads();
    for (int i = tid; i < KCLS * CCH; i += 256) atomicAdd(&g_k0[i], sk0[i]);
}

// -------- per-pixel softmax/NLL (tau pre-folded into prototypes) --------
__device__ __forceinline__ float pix_loss(const float* __restrict__ l,
                                          float ssum, unsigned m) {
    const float sc = 1.f / fmaxf(sqrtf(ssum), 1e-12f);
    float v[KCLS];
    float mx = -1e30f;
#pragma unroll
    for (int k = 0; k < KCLS; k++) {
        v[k] = l[k] * sc;
        mx = fmaxf(mx, v[k]);
    }
    float se = 0.f, sl = 0.f;
#pragma unroll
    for (int k = 0; k < KCLS; k++) {
        se += exp2f((v[k] - mx) * LOG2E);
        if (m & (1u << k)) sl += v[k];
    }
    return (float)__popc(m) * (mx + logf(se)) - sl;
}

// -------- launch 3: fp32 logits + softmax NLL, 4 px/thread (PROFILED) --------
// Reverted to the R3/R10-measured 101us configuration: LDG.128 pixel quads,
// duplicated-proto LDS.128, launch_bounds(256,2), 1024 exact-cover blocks.
__global__ __launch_bounds__(256, 2) void k_loss(const float* __restrict__ feat) {
    __shared__ unsigned long long sknd[KCLS * CCH];   // (kn/tau, kn/tau) duplicated
    __shared__ float sinv[KCLS];
    if (threadIdx.x < KCLS) {
        float s = 0.f;
#pragma unroll
        for (int c = 0; c < CCH; c++) {
            const float v = g_k0[threadIdx.x * CCH + c];
            s = fmaf(v, v, s);
        }
        sinv[threadIdx.x] = 1.f / (fmaxf(sqrtf(s), 1e-12f) * TAUF);
    }
    __syncthreads();
    for (int t = threadIdx.x; t < KCLS * CCH; t += 256) {
        const float v = g_k0[t] * sinv[t >> 6];
        sknd[t] = pack2(v, v);
    }
    __syncthreads();

    const int p4 = (blockIdx.x * 256 + threadIdx.x) * 4;   // 1024 blocks exactly
    const uint4 m  = *reinterpret_cast<const uint4*>(&g_maskbuf[p4]);
    const int   b  = p4 >> 18;
    const int   hw = p4 & (HW - 1);
    const float* fb = feat + (size_t)(b * CCH) * HW + hw;

    unsigned long long acca[KCLS], accb[KCLS];
#pragma unroll
    for (int k = 0; k < KCLS; k++) { acca[k] = 0ull; accb[k] = 0ull; }
    unsigned long long ssa = 0ull, ssb = 0ull;

#pragma unroll 2
    for (int c4 = 0; c4 < 16; c4++) {
        const float4 f0 = *reinterpret_cast<const float4*>(fb + (size_t)(4 * c4 + 0) * HW);
        const float4 f1 = *reinterpret_cast<const float4*>(fb + (size_t)(4 * c4 + 1) * HW);
        const float4 f2 = *reinterpret_cast<const float4*>(fb + (size_t)(4 * c4 + 2) * HW);
        const float4 f3 = *reinterpret_cast<const float4*>(fb + (size_t)(4 * c4 + 3) * HW);
        const unsigned long long A0 = pack2(f0.x, f0.y), B0 = pack2(f0.z, f0.w);
        const unsigned long long A1 = pack2(f1.x, f1.y), B1 = pack2(f1.z, f1.w);
        const unsigned long long A2 = pack2(f2.x, f2.y), B2 = pack2(f2.z, f2.w);
        const unsigned long long A3 = pack2(f3.x, f3.y), B3 = pack2(f3.z, f3.w);
        ffma2(ssa, A0, A0); ffma2(ssb, B0, B0);
        ffma2(ssa, A1, A1); ffma2(ssb, B1, B1);
        ffma2(ssa, A2, A2); ffma2(ssb, B2, B2);
        ffma2(ssa, A3, A3); ffma2(ssb, B3, B3);
#pragma unroll
        for (int k = 0; k < KCLS; k++) {
            const ulonglong2 k01 =
                *reinterpret_cast<const ulonglong2*>(&sknd[k * CCH + 4 * c4]);
            const ulonglong2 k23 =
                *reinterpret_cast<const ulonglong2*>(&sknd[k * CCH + 4 * c4 + 2]);
            ffma2(acca[k], A0, k01.x); ffma2(accb[k], B0, k01.x);
            ffma2(acca[k], A1, k01.y); ffma2(accb[k], B1, k01.y);
            ffma2(acca[k], A2, k23.x); ffma2(accb[k], B2, k23.x);
            ffma2(acca[k], A3, k23.y); ffma2(accb[k], B3, k23.y);
        }
    }

    float s0, s1, s2, s3;
    unpack2(ssa, s0, s1);
    unpack2(ssb, s2, s3);
    float l0[KCLS], l1[KCLS], l2[KCLS], l3[KCLS];
#pragma unroll
    for (int k = 0; k < KCLS; k++) {
        unpack2(acca[k], l0[k], l1[k]);
        unpack2(accb[k], l2[k], l3[k]);
    }
    float lsum = pix_loss(l0, s0, m.x) + pix_loss(l1, s1, m.y)
               + pix_loss(l2, s2, m.z) + pix_loss(l3, s3, m.w);

    // block reduction -> double atomic
#pragma unroll
    for (int o = 16; o; o >>= 1) lsum += __shfl_xor_sync(0xffffffffu, lsum, o);
    __shared__ float wsum[8];
    if ((threadIdx.x & 31) == 0) wsum[threadIdx.x >> 5] = lsum;
    __syncthreads();
    if (threadIdx.x < 8) {
        float v = wsum[threadIdx.x];
#pragma unroll
        for (int o = 4; o; o >>= 1) v += __shfl_xor_sync(0x000000ffu, v, o);
        if (threadIdx.x == 0) atomicAdd(&g_loss, (double)v);
    }
}

// -------- launch 4: finalize --------
__global__ void k_fin(float* out) {
    int s = 0;
    for (int t = threadIdx.x; t < 1024; t += 256) s += g_cnt[t];
#pragma unroll
    for (int o = 16; o; o >>= 1) s += __shfl_xor_sync(0xffffffffu, s, o);
    __shared__ int ws[8];
    if ((threadIdx.x & 31) == 0) ws[threadIdx.x >> 5] = s;
    __syncthreads();
    if (threadIdx.x == 0) {
        int np = 0;
#pragma unroll
        for (int w = 0; w < 8; w++) np += ws[w];
        out[0] = (float)(g_loss / (double)(np > 0 ? np : 1));
    }
}

extern "C" void kernel_launch(void* const* d_in, const int* in_sizes, int n_in,
                              void* d_out, int out_size) {
    const float* feat = (const float*)d_in[0];
    const int*   gt   = (const int*)d_in[1];
    float*       out  = (float*)d_out;

    k_mask     <<<NPIX / (256 * 4), 256>>>(gt);
    k_zero     <<<5, 256>>>();
    k_proto_mma<<<592, 256>>>(feat);
    k_loss     <<<NPIX / (256 * 4), 256>>>(feat);
    k_fin      <<<1, 256>>>(out);
}